// round 4
// baseline (speedup 1.0000x reference)
#include <cuda_runtime.h>
#include <stdint.h>

// Problem constants (match reference: B=1048576, Z_DIM=128, K=512)
#define ZDIM 128
#define KDIM 512

// Scratch for transposed a: at[k][d] = a[d][k].  512*128 floats = 256 KB.
__device__ float g_at[KDIM * ZDIM];

// ---------------------------------------------------------------------------
// Pre-pass: transpose a (ZDIM x KDIM row-major) -> g_at (KDIM x ZDIM row-major)
// so the per-row gather becomes a contiguous, coalesced 512B read that stays
// resident in L2 (256 KB total).
// ---------------------------------------------------------------------------
__global__ void transpose_a_kernel(const float* __restrict__ a) {
    int tid = blockIdx.x * blockDim.x + threadIdx.x;   // 0 .. K*Z-1
    if (tid >= KDIM * ZDIM) return;
    int k = tid / ZDIM;      // consecutive tids share k -> coalesced write
    int d = tid % ZDIM;
    g_at[tid] = a[d * KDIM + k];   // strided read (fine; tiny tensor, one pass)
}

// ---------------------------------------------------------------------------
// Main kernel: warp-per-row. 32 lanes x float4 = 128 floats = one row.
//   out[b] = z[b] + at[idx[b]] * scale[b]
// z/out: fully coalesced 512B per warp. at row: coalesced 512B, L2-hit.
// NOTE: labels_idx is int32 on device (JAX x64 disabled demotes int64->int32).
// ---------------------------------------------------------------------------
__global__ void __launch_bounds__(256, 8)
fused_gather_axpy_kernel(const float4* __restrict__ z4,
                         const int* __restrict__ labels_idx,
                         const float* __restrict__ labels_scale,
                         float4* __restrict__ out4,
                         int n_rows) {
    const int lane = threadIdx.x & 31;
    const int warp = (blockIdx.x * (blockDim.x >> 5)) + (threadIdx.x >> 5);
    if (warp >= n_rows) return;

    // Broadcast loads (same address across warp -> single transaction)
    const int   idx = labels_idx[warp];
    const float s   = labels_scale[warp];

    const float4* __restrict__ at4 =
        reinterpret_cast<const float4*>(g_at) + (size_t)idx * (ZDIM / 4);

    const size_t off = (size_t)warp * (ZDIM / 4) + lane;
    float4 zv = z4[off];
    float4 av = at4[lane];

    float4 o;
    o.x = fmaf(av.x, s, zv.x);
    o.y = fmaf(av.y, s, zv.y);
    o.z = fmaf(av.z, s, zv.z);
    o.w = fmaf(av.w, s, zv.w);

    out4[off] = o;
}

extern "C" void kernel_launch(void* const* d_in, const int* in_sizes, int n_in,
                              void* d_out, int out_size) {
    const float* z     = (const float*)d_in[0];   // (B, 128) f32
    const float* a     = (const float*)d_in[1];   // (128, 512) f32
    const int*   idx   = (const int*)d_in[2];     // (B,) int32 on device
    const float* scale = (const float*)d_in[3];   // (B,) f32
    float*       out   = (float*)d_out;

    const int B = in_sizes[2];   // number of rows (labels count)

    // 1) transpose a into L2-resident scratch
    {
        int n = KDIM * ZDIM;
        transpose_a_kernel<<<(n + 255) / 256, 256>>>(a);
    }

    // 2) fused gather + axpy, warp per row (8 rows per 256-thread block)
    {
        int warps_per_block = 256 / 32;
        int blocks = (B + warps_per_block - 1) / warps_per_block;
        fused_gather_axpy_kernel<<<blocks, 256>>>(
            (const float4*)z, idx, scale, (float4*)out, B);
    }
}

// round 5
// speedup vs baseline: 1.0045x; 1.0045x over previous
#include <cuda_runtime.h>
#include <stdint.h>

// Problem constants (match reference: B=1048576, Z_DIM=128, K=512)
#define ZDIM 128
#define KDIM 512

// Scratch for transposed a: at[k][d] = a[d][k].  512*128 floats = 256 KB.
__device__ float g_at[KDIM * ZDIM];

// ---------------------------------------------------------------------------
// Pre-pass: transpose a (ZDIM x KDIM row-major) -> g_at (KDIM x ZDIM row-major)
// so the per-row gather becomes a contiguous, coalesced 512B read that stays
// resident in L2 (256 KB total).
// ---------------------------------------------------------------------------
__global__ void transpose_a_kernel(const float* __restrict__ a) {
    int tid = blockIdx.x * blockDim.x + threadIdx.x;   // 0 .. K*Z-1
    if (tid >= KDIM * ZDIM) return;
    int k = tid / ZDIM;      // consecutive tids share k -> coalesced write
    int d = tid % ZDIM;
    g_at[tid] = a[d * KDIM + k];   // strided read (fine; tiny tensor, one pass)
}

// ---------------------------------------------------------------------------
// Main kernel: warp-per-row. 32 lanes x float4 = 128 floats = one row.
//   out[b] = z[b] + at[idx[b]] * scale[b]
// z/out: fully coalesced 512B per warp. at row: coalesced 512B, L2-hit.
// NOTE: labels_idx is int32 on device (JAX x64 disabled demotes int64->int32).
// ---------------------------------------------------------------------------
__global__ void __launch_bounds__(256, 8)
fused_gather_axpy_kernel(const float4* __restrict__ z4,
                         const int* __restrict__ labels_idx,
                         const float* __restrict__ labels_scale,
                         float4* __restrict__ out4,
                         int n_rows) {
    const int lane = threadIdx.x & 31;
    const int warp = (blockIdx.x * (blockDim.x >> 5)) + (threadIdx.x >> 5);
    if (warp >= n_rows) return;

    // Broadcast loads (same address across warp -> single transaction)
    const int   idx = labels_idx[warp];
    const float s   = labels_scale[warp];

    const float4* __restrict__ at4 =
        reinterpret_cast<const float4*>(g_at) + (size_t)idx * (ZDIM / 4);

    const size_t off = (size_t)warp * (ZDIM / 4) + lane;
    float4 zv = z4[off];
    float4 av = at4[lane];

    float4 o;
    o.x = fmaf(av.x, s, zv.x);
    o.y = fmaf(av.y, s, zv.y);
    o.z = fmaf(av.z, s, zv.z);
    o.w = fmaf(av.w, s, zv.w);

    out4[off] = o;
}

extern "C" void kernel_launch(void* const* d_in, const int* in_sizes, int n_in,
                              void* d_out, int out_size) {
    const float* z     = (const float*)d_in[0];   // (B, 128) f32
    const float* a     = (const float*)d_in[1];   // (128, 512) f32
    const int*   idx   = (const int*)d_in[2];     // (B,) int32 on device
    const float* scale = (const float*)d_in[3];   // (B,) f32
    float*       out   = (float*)d_out;

    const int B = in_sizes[2];   // number of rows (labels count)

    // 1) transpose a into L2-resident scratch
    {
        int n = KDIM * ZDIM;
        transpose_a_kernel<<<(n + 255) / 256, 256>>>(a);
    }

    // 2) fused gather + axpy, warp per row (8 rows per 256-thread block)
    {
        int warps_per_block = 256 / 32;
        int blocks = (B + warps_per_block - 1) / warps_per_block;
        fused_gather_axpy_kernel<<<blocks, 256>>>(
            (const float4*)z, idx, scale, (float4*)out, B);
    }
}

// round 6
// speedup vs baseline: 1.2484x; 1.2428x over previous
#include <cuda_runtime.h>
#include <stdint.h>

// Problem constants (match reference: B=1048576, Z_DIM=128, K=512)
#define ZDIM 128
#define KDIM 512
#define ROWS_PER_WARP 4

// Scratch for transposed a: at[k][d] = a[d][k].  512*128 floats = 256 KB.
__device__ float g_at[KDIM * ZDIM];

// ---------------------------------------------------------------------------
// Pre-pass: transpose a (ZDIM x KDIM row-major) -> g_at (KDIM x ZDIM row-major)
// ---------------------------------------------------------------------------
__global__ void transpose_a_kernel(const float* __restrict__ a) {
    int tid = blockIdx.x * blockDim.x + threadIdx.x;   // 0 .. K*Z-1
    if (tid >= KDIM * ZDIM) return;
    int k = tid / ZDIM;      // consecutive tids share k -> coalesced write
    int d = tid % ZDIM;
    g_at[tid] = a[d * KDIM + k];
}

// ---------------------------------------------------------------------------
// Main kernel: warp processes 4 rows. 32 lanes x float4 = 128 floats per row.
//   out[b] = z[b] + at[idx[b]] * scale[b]
// Front-batched independent loads (4x idx, 4x z, 4x at) to raise MLP and
// hide DRAM latency. z/out use streaming hints (.cs) so the L2 keeps the
// 256KB gather table + idx/scale metadata resident.
// ---------------------------------------------------------------------------
__global__ void __launch_bounds__(256, 8)
fused_gather_axpy_kernel(const float4* __restrict__ z4,
                         const int* __restrict__ labels_idx,
                         const float* __restrict__ labels_scale,
                         float4* __restrict__ out4,
                         int n_rows) {
    const int lane = threadIdx.x & 31;
    const int warp_g = blockIdx.x * (blockDim.x >> 5) + (threadIdx.x >> 5);
    const int row0 = warp_g * ROWS_PER_WARP;
    if (row0 >= n_rows) return;

    const float4* __restrict__ at4 = reinterpret_cast<const float4*>(g_at);

    if (row0 + ROWS_PER_WARP <= n_rows) {
        // ---- fast path: 4 full rows, all loads front-batched ----
        int   i0 = __ldg(&labels_idx[row0 + 0]);
        int   i1 = __ldg(&labels_idx[row0 + 1]);
        int   i2 = __ldg(&labels_idx[row0 + 2]);
        int   i3 = __ldg(&labels_idx[row0 + 3]);
        float s0 = __ldg(&labels_scale[row0 + 0]);
        float s1 = __ldg(&labels_scale[row0 + 1]);
        float s2 = __ldg(&labels_scale[row0 + 2]);
        float s3 = __ldg(&labels_scale[row0 + 3]);

        const size_t base = (size_t)row0 * (ZDIM / 4) + lane;
        float4 z0 = __ldcs(&z4[base + 0 * (ZDIM / 4)]);
        float4 z1 = __ldcs(&z4[base + 1 * (ZDIM / 4)]);
        float4 z2 = __ldcs(&z4[base + 2 * (ZDIM / 4)]);
        float4 z3 = __ldcs(&z4[base + 3 * (ZDIM / 4)]);

        float4 a0 = __ldg(&at4[(size_t)i0 * (ZDIM / 4) + lane]);
        float4 a1 = __ldg(&at4[(size_t)i1 * (ZDIM / 4) + lane]);
        float4 a2 = __ldg(&at4[(size_t)i2 * (ZDIM / 4) + lane]);
        float4 a3 = __ldg(&at4[(size_t)i3 * (ZDIM / 4) + lane]);

        float4 o0, o1, o2, o3;
        o0.x = fmaf(a0.x, s0, z0.x); o0.y = fmaf(a0.y, s0, z0.y);
        o0.z = fmaf(a0.z, s0, z0.z); o0.w = fmaf(a0.w, s0, z0.w);
        o1.x = fmaf(a1.x, s1, z1.x); o1.y = fmaf(a1.y, s1, z1.y);
        o1.z = fmaf(a1.z, s1, z1.z); o1.w = fmaf(a1.w, s1, z1.w);
        o2.x = fmaf(a2.x, s2, z2.x); o2.y = fmaf(a2.y, s2, z2.y);
        o2.z = fmaf(a2.z, s2, z2.z); o2.w = fmaf(a2.w, s2, z2.w);
        o3.x = fmaf(a3.x, s3, z3.x); o3.y = fmaf(a3.y, s3, z3.y);
        o3.z = fmaf(a3.z, s3, z3.z); o3.w = fmaf(a3.w, s3, z3.w);

        __stcs(&out4[base + 0 * (ZDIM / 4)], o0);
        __stcs(&out4[base + 1 * (ZDIM / 4)], o1);
        __stcs(&out4[base + 2 * (ZDIM / 4)], o2);
        __stcs(&out4[base + 3 * (ZDIM / 4)], o3);
    } else {
        // ---- tail path (only if n_rows not a multiple of 4) ----
        for (int r = row0; r < n_rows; ++r) {
            int   i = __ldg(&labels_idx[r]);
            float s = __ldg(&labels_scale[r]);
            size_t off = (size_t)r * (ZDIM / 4) + lane;
            float4 zv = __ldcs(&z4[off]);
            float4 av = __ldg(&at4[(size_t)i * (ZDIM / 4) + lane]);
            float4 o;
            o.x = fmaf(av.x, s, zv.x);
            o.y = fmaf(av.y, s, zv.y);
            o.z = fmaf(av.z, s, zv.z);
            o.w = fmaf(av.w, s, zv.w);
            __stcs(&out4[off], o);
        }
    }
}

extern "C" void kernel_launch(void* const* d_in, const int* in_sizes, int n_in,
                              void* d_out, int out_size) {
    const float* z     = (const float*)d_in[0];   // (B, 128) f32
    const float* a     = (const float*)d_in[1];   // (128, 512) f32
    const int*   idx   = (const int*)d_in[2];     // (B,) int32 on device
    const float* scale = (const float*)d_in[3];   // (B,) f32
    float*       out   = (float*)d_out;

    const int B = in_sizes[2];   // number of rows

    // 1) transpose a into L2-resident scratch
    {
        int n = KDIM * ZDIM;
        transpose_a_kernel<<<(n + 255) / 256, 256>>>(a);
    }

    // 2) fused gather + axpy: warp handles 4 rows, 8 warps/block
    {
        int warps_per_block = 256 / 32;
        int rows_per_block  = warps_per_block * ROWS_PER_WARP;   // 32
        int blocks = (B + rows_per_block - 1) / rows_per_block;  // 32768
        fused_gather_axpy_kernel<<<blocks, 256>>>(
            (const float4*)z, idx, scale, (float4*)out, B);
    }
}

// round 7
// speedup vs baseline: 1.2595x; 1.0089x over previous
#include <cuda_runtime.h>
#include <stdint.h>

// Problem constants (match reference: B=1048576, Z_DIM=128, K=512)
#define ZDIM 128
#define KDIM 512
#define ROWS_PER_WARP 8

// Scratch for transposed a: at[k][d] = a[d][k].  512*128 floats = 256 KB.
__device__ float g_at[KDIM * ZDIM];

// ---------------------------------------------------------------------------
// Pre-pass: 32x32 smem-tiled transpose, coalesced on both read and write.
// a is (ZDIM x KDIM) row-major; g_at is (KDIM x ZDIM) row-major.
// Grid: (KDIM/32, ZDIM/32) = (16, 4), block (32, 8).
// ---------------------------------------------------------------------------
__global__ void transpose_a_kernel(const float* __restrict__ a) {
    __shared__ float tile[32][33];   // +1 pad: no bank conflicts

    int kBase = blockIdx.x * 32;
    int dBase = blockIdx.y * 32;

    // Read: rows of a (d-major), coalesced along k.
    #pragma unroll
    for (int r = 0; r < 32; r += 8) {
        int d = dBase + threadIdx.y + r;
        int k = kBase + threadIdx.x;
        tile[threadIdx.y + r][threadIdx.x] = a[d * KDIM + k];
    }
    __syncthreads();

    // Write: rows of g_at (k-major), coalesced along d.
    #pragma unroll
    for (int r = 0; r < 32; r += 8) {
        int k = kBase + threadIdx.y + r;
        int d = dBase + threadIdx.x;
        g_at[k * ZDIM + d] = tile[threadIdx.x][threadIdx.y + r];
    }
}

// ---------------------------------------------------------------------------
// Main kernel: warp processes 8 rows. 32 lanes x float4 = 128 floats per row.
//   out[b] = z[b] + at[idx[b]] * scale[b]
// All 8 z-loads and 8 at-loads are front-batched (MLP=16 wide loads/warp)
// before any FMA, then 8 streaming stores. z/out use .cs so L2 stays
// dedicated to the 256KB gather table + idx/scale metadata.
// ---------------------------------------------------------------------------
__global__ void __launch_bounds__(256, 3)
fused_gather_axpy_kernel(const float4* __restrict__ z4,
                         const int* __restrict__ labels_idx,
                         const float* __restrict__ labels_scale,
                         float4* __restrict__ out4,
                         int n_rows) {
    const int lane = threadIdx.x & 31;
    const int warp_g = blockIdx.x * (blockDim.x >> 5) + (threadIdx.x >> 5);
    const int row0 = warp_g * ROWS_PER_WARP;
    if (row0 >= n_rows) return;

    const float4* __restrict__ at4 = reinterpret_cast<const float4*>(g_at);

    if (row0 + ROWS_PER_WARP <= n_rows) {
        // ---- fast path: 8 full rows, every load issued before any FMA ----
        int   idx[ROWS_PER_WARP];
        float scl[ROWS_PER_WARP];
        #pragma unroll
        for (int r = 0; r < ROWS_PER_WARP; ++r) idx[r] = __ldg(&labels_idx[row0 + r]);
        #pragma unroll
        for (int r = 0; r < ROWS_PER_WARP; ++r) scl[r] = __ldg(&labels_scale[row0 + r]);

        const size_t base = (size_t)row0 * (ZDIM / 4) + lane;

        float4 zv[ROWS_PER_WARP];
        #pragma unroll
        for (int r = 0; r < ROWS_PER_WARP; ++r)
            zv[r] = __ldcs(&z4[base + (size_t)r * (ZDIM / 4)]);

        float4 av[ROWS_PER_WARP];
        #pragma unroll
        for (int r = 0; r < ROWS_PER_WARP; ++r)
            av[r] = __ldg(&at4[(size_t)idx[r] * (ZDIM / 4) + lane]);

        #pragma unroll
        for (int r = 0; r < ROWS_PER_WARP; ++r) {
            float4 o;
            o.x = fmaf(av[r].x, scl[r], zv[r].x);
            o.y = fmaf(av[r].y, scl[r], zv[r].y);
            o.z = fmaf(av[r].z, scl[r], zv[r].z);
            o.w = fmaf(av[r].w, scl[r], zv[r].w);
            __stcs(&out4[base + (size_t)r * (ZDIM / 4)], o);
        }
    } else {
        // ---- tail path (n_rows not a multiple of ROWS_PER_WARP) ----
        for (int r = row0; r < n_rows; ++r) {
            int   i = __ldg(&labels_idx[r]);
            float s = __ldg(&labels_scale[r]);
            size_t off = (size_t)r * (ZDIM / 4) + lane;
            float4 zvv = __ldcs(&z4[off]);
            float4 avv = __ldg(&at4[(size_t)i * (ZDIM / 4) + lane]);
            float4 o;
            o.x = fmaf(avv.x, s, zvv.x);
            o.y = fmaf(avv.y, s, zvv.y);
            o.z = fmaf(avv.z, s, zvv.z);
            o.w = fmaf(avv.w, s, zvv.w);
            __stcs(&out4[off], o);
        }
    }
}

extern "C" void kernel_launch(void* const* d_in, const int* in_sizes, int n_in,
                              void* d_out, int out_size) {
    const float* z     = (const float*)d_in[0];   // (B, 128) f32
    const float* a     = (const float*)d_in[1];   // (128, 512) f32
    const int*   idx   = (const int*)d_in[2];     // (B,) int32 on device
    const float* scale = (const float*)d_in[3];   // (B,) f32
    float*       out   = (float*)d_out;

    const int B = in_sizes[2];   // number of rows

    // 1) transpose a into L2-resident scratch (tiled, coalesced both ways)
    {
        dim3 grid(KDIM / 32, ZDIM / 32);   // (16, 4)
        dim3 block(32, 8);
        transpose_a_kernel<<<grid, block>>>(a);
    }

    // 2) fused gather + axpy: warp handles 8 rows, 8 warps/block
    {
        int warps_per_block = 256 / 32;
        int rows_per_block  = warps_per_block * ROWS_PER_WARP;   // 64
        int blocks = (B + rows_per_block - 1) / rows_per_block;  // 16384
        fused_gather_axpy_kernel<<<blocks, 256>>>(
            (const float4*)z, idx, scale, (float4*)out, B);
    }
}